// round 6
// baseline (speedup 1.0000x reference)
#include <cuda_runtime.h>
#include <math.h>

#define FF 15
#define HH 128
#define LL 12
#define NBINS 16
#define MM 47            // 3*NB - 1
#define OUTW (FF*MM)     // 705
#define FP 48            // padded per-feature width
#define NFP 16           // padded feature count
#define OUTWP (NFP*FP)   // 768
#define TAILV 3.0f
#define MINW 0.001f
#define MINH 0.001f
#define MIND 0.001f
#define SPB 128          // samples per block
#define TL 132           // row stride for h/t buffers
#define XL 16            // row stride for x buffer
#define NT 256           // threads per CTA

typedef unsigned long long ull;

// Pre-masked, transposed, padded weights (scratch)
__device__ float g_Wi[LL * 16 * HH];        // [l][k(16)][j]
__device__ float g_Wr[LL * 4 * HH * HH];    // [l][blk*2+sub][k][j]
__device__ float g_Wo[LL * HH * OUTWP];     // [l][k][f*48+m]
__device__ float g_bo[LL * OUTWP];          // padded out bias

// ---------------------------------------------------------------------------
__global__ void prep_kernel(const float* __restrict__ Wi,
                            const float* __restrict__ Wr,
                            const float* __restrict__ Wo,
                            const float* __restrict__ bo)
{
    const int n1 = LL * 16 * HH;
    const int n2 = LL * 4 * HH * HH;
    const int n3 = LL * HH * OUTWP;
    const int n4 = LL * OUTWP;
    for (int i = blockIdx.x * blockDim.x + threadIdx.x; i < n1 + n2 + n3 + n4;
         i += gridDim.x * blockDim.x) {
        if (i < n1) {
            int j = i % HH;
            int k = (i / HH) % 16;
            int l = i / (16 * HH);
            float v = 0.f;
            if (k < FF) {
                int degh = j % (FF - 1) + 1;
                if (degh >= k + 1) v = Wi[(l * HH + j) * FF + k];
            }
            g_Wi[i] = v;
        } else if (i < n1 + n2) {
            int t = i - n1;
            int j = t % HH;
            int k = (t / HH) % HH;
            int m = t / (HH * HH);
            int degj = j % (FF - 1) + 1;
            int degk = k % (FF - 1) + 1;
            g_Wr[t] = (degj >= degk) ? Wr[(m * HH + j) * HH + k] : 0.f;
        } else if (i < n1 + n2 + n3) {
            int t = i - n1 - n2;
            int c = t % OUTWP;              // f*48+m
            int k = (t / OUTWP) % HH;
            int l = t / (HH * OUTWP);
            int f = c / FP, m = c % FP;
            float v = 0.f;
            if (f < FF && m < MM) {
                int degk = k % (FF - 1) + 1;
                if (f + 1 > degk) v = Wo[(l * OUTW + f * MM + m) * HH + k];
            }
            g_Wo[t] = v;
        } else {
            int t = i - n1 - n2 - n3;
            int c = t % OUTWP;
            int l = t / OUTWP;
            int f = c / FP, m = c % FP;
            g_bo[t] = (f < FF && m < MM) ? bo[l * OUTW + f * MM + m] : 0.f;
        }
    }
}

// ---------------------------------------------------------------------------
__device__ __forceinline__ void fma2(ull& d, ull a, ull b)
{
    asm("fma.rn.f32x2 %0, %1, %2, %0;" : "+l"(d) : "l"(a), "l"(b));
}
__device__ __forceinline__ ull pack2(float v)
{
    ull r; asm("mov.b64 %0, {%1, %1};" : "=l"(r) : "f"(v)); return r;
}
__device__ __forceinline__ ull packf2(float a, float b)
{
    ull r; asm("mov.b64 %0, {%1, %2};" : "=l"(r) : "f"(a), "f"(b)); return r;
}

// ---------------------------------------------------------------------------
// Weight slab load: 4 k-rows x NP ull pairs.
// VEC4: 2x LDG.128 per k-row (requires c0 16B-aligned, NP even).
// ---------------------------------------------------------------------------
template <int NP, bool VEC4>
__device__ __forceinline__ void loadW(ull (&w)[4][NP],
                                      const float* __restrict__ Wg,
                                      int wld, int c0, int k0)
{
#pragma unroll
    for (int kk = 0; kk < 4; kk++) {
        const float* wr = Wg + (k0 + kk) * wld + c0;
        if (VEC4) {
#pragma unroll
            for (int j = 0; j < NP; j += 2) {
                ulonglong2 v = __ldg((const ulonglong2*)(wr + 2 * j));
                w[kk][j] = v.x;
                w[kk][j + 1] = v.y;
            }
        } else {
#pragma unroll
            for (int j = 0; j < NP; j++)
                w[kk][j] = __ldg((const ull*)(wr + 2 * j));
        }
    }
}

// Compute one 4-wide k-chunk for 8 rows.
template <int NP, bool RELU>
__device__ __forceinline__ void computeChunk(ull (&acc)[8][NP],
                                             const float* __restrict__ As,
                                             int ald, int r0, int k0,
                                             const ull (&w)[4][NP])
{
#pragma unroll
    for (int i = 0; i < 8; i++) {
        float4 a = *(const float4*)&As[(r0 + i) * ald + k0];
        if (RELU) {
            a.x = fmaxf(a.x, 0.f);
            a.y = fmaxf(a.y, 0.f);
            a.z = fmaxf(a.z, 0.f);
            a.w = fmaxf(a.w, 0.f);
        }
        ull a0 = pack2(a.x), a1 = pack2(a.y), a2 = pack2(a.z), a3 = pack2(a.w);
#pragma unroll
        for (int j = 0; j < NP; j++) fma2(acc[i][j], a0, w[0][j]);
#pragma unroll
        for (int j = 0; j < NP; j++) fma2(acc[i][j], a1, w[1][j]);
#pragma unroll
        for (int j = 0; j < NP; j++) fma2(acc[i][j], a2, w[2][j]);
#pragma unroll
        for (int j = 0; j < NP; j++) fma2(acc[i][j], a3, w[3][j]);
    }
}

// ---------------------------------------------------------------------------
// Packed-f32x2 GEMM with double-buffered weight prefetch.
// C[128 x 16*NC] (+)= op(A[128 x K]) @ W[K x .] + bias
// 256 threads: ty = tid>>4 -> 8 rows each; tx = tid&15 -> NC cols.
// K must be a multiple of 8.
// ---------------------------------------------------------------------------
template <int K, int NC, bool VEC4, bool RELU, bool ACC>
__device__ __forceinline__ void gemm2(const float* __restrict__ As, int ald,
                                      const float* __restrict__ Wg, int wld,
                                      const float* __restrict__ bias,
                                      float* __restrict__ Cs, int cld,
                                      int tx, int ty)
{
    constexpr int NP = NC / 2;
    const int c0 = tx * NC;
    const int r0 = ty * 8;

    ull acc[8][NP];
#pragma unroll
    for (int j = 0; j < NP; j++) {
        float2 b = *(const float2*)&bias[c0 + 2 * j];
#pragma unroll
        for (int i = 0; i < 8; i++) {
            float2 p = make_float2(0.f, 0.f);
            if (ACC) p = *(const float2*)&Cs[(r0 + i) * cld + c0 + 2 * j];
            acc[i][j] = packf2(b.x + p.x, b.y + p.y);
        }
    }

    ull wa[4][NP], wb[4][NP];
    loadW<NP, VEC4>(wa, Wg, wld, c0, 0);

#pragma unroll 1
    for (int k0 = 0; k0 < K; k0 += 8) {
        loadW<NP, VEC4>(wb, Wg, wld, c0, k0 + 4);
        computeChunk<NP, RELU>(acc, As, ald, r0, k0, wa);
        if (k0 + 8 < K) loadW<NP, VEC4>(wa, Wg, wld, c0, k0 + 8);
        computeChunk<NP, RELU>(acc, As, ald, r0, k0 + 4, wb);
    }

#pragma unroll
    for (int i = 0; i < 8; i++)
#pragma unroll
        for (int j = 0; j < NP; j++)
            *(float2*)&Cs[(r0 + i) * cld + c0 + 2 * j] = *(float2*)&acc[i][j];
}

// ---------------------------------------------------------------------------
__device__ __forceinline__ float softplusf(float v)
{
    return (v > 15.f) ? v : log1pf(__expf(v));
}

// Rational-quadratic spline, register-only scratch. p = 47 raw params (smem).
__device__ void rqs_reg(const float* __restrict__ p,
                        float* __restrict__ xp, float* __restrict__ ldp)
{
    float x = *xp;
    bool inside = (x >= -TAILV) && (x <= TAILV);
    float xc = fminf(fmaxf(x, -TAILV), TAILV);

    float ew[NBINS], eh[NBINS];
    float mw = p[0], mh = p[16];
#pragma unroll
    for (int i = 1; i < NBINS; i++) { mw = fmaxf(mw, p[i]); mh = fmaxf(mh, p[16 + i]); }
    float Sw = 0.f, Sh = 0.f;
#pragma unroll
    for (int i = 0; i < NBINS; i++) {
        ew[i] = __expf(p[i] - mw);      Sw += ew[i];
        eh[i] = __expf(p[16 + i] - mh); Sh += eh[i];
    }
    float scw = (1.f - MINW * NBINS) / Sw;
    float sch = (1.f - MINH * NBINS) / Sh;

    int idx = 0;
    float cwlo = -TAILV, cwhi = TAILV;
    bool found = false;
    float cacc = 0.f;
#pragma unroll
    for (int i = 0; i < NBINS - 1; i++) {
        cacc += MINW + scw * ew[i];
        float cw = 6.f * cacc - 3.f;
        if (xc >= cw) { idx++; cwlo = cw; }
        else if (!found) { cwhi = cw; found = true; }
    }
    float chlo = -TAILV, chhi = TAILV;
    float hacc = 0.f;
#pragma unroll
    for (int i = 0; i < NBINS - 1; i++) {
        hacc += MINH + sch * eh[i];
        float ch = 6.f * hacc - 3.f;
        if (i == idx - 1) chlo = ch;
        if (i == idx)     chhi = ch;
    }

    float inw = cwhi - cwlo;
    float inh = chhi - chlo;
    float delta = inh / inw;
    float ind  = (idx == 0)          ? 1.f : MIND + softplusf(p[32 + idx - 1]);
    float ind1 = (idx == NBINS - 1)  ? 1.f : MIND + softplusf(p[32 + idx]);

    float th   = (xc - cwlo) / inw;
    float omt  = 1.f - th;
    float tomt = th * omt;
    float num  = inh * (delta * th * th + ind * tomt);
    float den  = delta + (ind + ind1 - 2.f * delta) * tomt;
    float y    = chlo + num / den;
    float dnum = delta * delta * (ind1 * th * th + 2.f * delta * tomt + ind * omt * omt);
    float lad  = __logf(dnum) - 2.f * __logf(den);

    *xp = inside ? y : x;
    if (inside) atomicAdd(ldp, lad);
}

// ---------------------------------------------------------------------------
__global__ void __launch_bounds__(NT, 1)
flow_kernel(const float* __restrict__ x_in,
            const float* __restrict__ b_init,
            const float* __restrict__ b_res,
            float* __restrict__ out, int batch)
{
    extern __shared__ float sm[];
    float* xs   = sm;                      // SPB * XL
    float* hbuf = xs + SPB * XL;           // SPB * TL
    float* tbuf = hbuf + SPB * TL;         // SPB * TL
    float* ldv  = tbuf + SPB * TL;         // SPB

    int tid = threadIdx.x;
    int tx = tid & 15, ty = tid >> 4;
    int base = blockIdx.x * SPB;

    for (int i = tid; i < SPB * FF; i += NT) {
        int s = i / FF, f = i % FF;
        xs[s * XL + f] = x_in[(base + s) * FF + f];
    }
    for (int i = tid; i < SPB; i += NT) { xs[i * XL + FF] = 0.f; ldv[i] = 0.f; }
    __syncthreads();

    for (int l = 0; l < LL; l++) {
        // feature reversal (each thread owns a full row)
        if (tid < SPB) {
            float v[FF];
#pragma unroll
            for (int f = 0; f < FF; f++) v[f] = xs[tid * XL + f];
#pragma unroll
            for (int f = 0; f < FF; f++) xs[tid * XL + f] = v[FF - 1 - f];
        }
        __syncthreads();

        // h = xs @ Wi^T + bi   (K=16, N=128, NC=8, vec4 weights)
        gemm2<16, 8, true, false, false>(xs, XL, g_Wi + l * 16 * HH, HH,
                                         b_init + l * HH, hbuf, TL, tx, ty);
        __syncthreads();

        const float* wr = g_Wr + l * 4 * HH * HH;
        const float* br = b_res + l * 4 * HH;

        gemm2<128, 8, true, true, false>(hbuf, TL, wr, HH, br, tbuf, TL, tx, ty);
        __syncthreads();
        gemm2<128, 8, true, true, true>(tbuf, TL, wr + HH * HH, HH, br + HH,
                                        hbuf, TL, tx, ty);
        __syncthreads();
        gemm2<128, 8, true, true, false>(hbuf, TL, wr + 2 * HH * HH, HH,
                                         br + 2 * HH, tbuf, TL, tx, ty);
        __syncthreads();
        gemm2<128, 8, true, true, true>(tbuf, TL, wr + 3 * HH * HH, HH,
                                        br + 3 * HH, hbuf, TL, tx, ty);
        __syncthreads();

        // output head: 8 chunks of 2 padded features (96 cols), fused RQS
        for (int c = 0; c < 8; c++) {
            gemm2<128, 6, false, false, false>(hbuf, TL,
                                               g_Wo + l * HH * OUTWP + c * 96,
                                               OUTWP,
                                               g_bo + l * OUTWP + c * 96,
                                               tbuf, TL, tx, ty);
            __syncthreads();
            {
                int s = tid >> 1, q = tid & 1;
                int f = 2 * c + q;
                if (f < FF)
                    rqs_reg(&tbuf[s * TL + q * FP], &xs[s * XL + f], &ldv[s]);
            }
            __syncthreads();
        }
    }

    for (int i = tid; i < SPB * FF; i += NT) {
        int s = i / FF, f = i % FF;
        out[(base + s) * FF + f] = xs[s * XL + f];
    }
    if (tid < SPB) out[batch * FF + base + tid] = ldv[tid];
}

static const int SMEM_BYTES = (SPB * XL + 2 * SPB * TL + SPB) * (int)sizeof(float);

extern "C" void kernel_launch(void* const* d_in, const int* in_sizes, int n_in,
                              void* d_out, int out_size)
{
    const float* x  = (const float*)d_in[0];
    const float* Wi = (const float*)d_in[1];
    const float* bi = (const float*)d_in[2];
    const float* Wr = (const float*)d_in[3];
    const float* br = (const float*)d_in[4];
    const float* Wo = (const float*)d_in[5];
    const float* bo = (const float*)d_in[6];
    float* out = (float*)d_out;

    int batch = in_sizes[0] / FF;

    cudaFuncSetAttribute(flow_kernel,
                         cudaFuncAttributeMaxDynamicSharedMemorySize, SMEM_BYTES);

    prep_kernel<<<2048, 256>>>(Wi, Wr, Wo, bo);
    flow_kernel<<<batch / SPB, NT, SMEM_BYTES>>>(x, bi, br, out, batch);
}

// round 7
// speedup vs baseline: 1.4752x; 1.4752x over previous
#include <cuda_runtime.h>
#include <math.h>

#define FF 15
#define HH 128
#define LL 12
#define NBINS 16
#define MM 47            // 3*NB - 1
#define OUTW (FF*MM)     // 705
#define FP 48            // padded per-feature width
#define NFP 16           // padded feature count
#define OUTWP (NFP*FP)   // 768
#define TAILV 3.0f
#define MINW 0.001f
#define MINH 0.001f
#define MIND 0.001f
#define SPB 128          // samples per block
#define TL 132           // row stride for h/t buffers
#define XL 16            // row stride for x buffer
#define NT 256           // threads per CTA

typedef unsigned long long ull;

// Hidden units permuted sorted-by-degree (exact similarity transform).
// degnew(j): degree of new hidden index j (ascending).
// cumcnt(d): #hidden units with degree <= d.  perm(j): new -> old index.
__host__ __device__ __forceinline__ int cumcnt(int d)
{
    return (d <= 2) ? 10 * d : 9 * d + 2;
}
__host__ __device__ __forceinline__ int degnew(int j)
{
    return (j < 20) ? (j / 10 + 1) : ((j - 2) / 9 + 1);
}
__host__ __device__ __forceinline__ int permj(int j)
{
    int d = degnew(j);
    int t = j - cumcnt(d - 1);
    return (d - 1) + 14 * t;
}

// Pre-masked, transposed, permuted, padded weights (scratch)
__device__ float g_Wi[LL * 16 * HH];        // [l][k(16)][j']
__device__ float g_Wr[LL * 4 * HH * HH];    // [l][blk*2+sub][k'][j']
__device__ float g_Wo[LL * HH * OUTWP];     // [l][k'][f*48+m]
__device__ float g_bo[LL * OUTWP];          // padded out bias
__device__ float g_bi[LL * HH];             // permuted init bias
__device__ float g_br[LL * 4 * HH];         // permuted res bias

// ---------------------------------------------------------------------------
__global__ void prep_kernel(const float* __restrict__ Wi,
                            const float* __restrict__ bi,
                            const float* __restrict__ Wr,
                            const float* __restrict__ br,
                            const float* __restrict__ Wo,
                            const float* __restrict__ bo)
{
    const int n1 = LL * 16 * HH;
    const int n2 = LL * 4 * HH * HH;
    const int n3 = LL * HH * OUTWP;
    const int n4 = LL * OUTWP;
    const int n5 = LL * HH;
    const int n6 = LL * 4 * HH;
    const int ntot = n1 + n2 + n3 + n4 + n5 + n6;
    for (int i = blockIdx.x * blockDim.x + threadIdx.x; i < ntot;
         i += gridDim.x * blockDim.x) {
        if (i < n1) {
            int j = i % HH;               // new hidden index
            int k = (i / HH) % 16;        // input feature
            int l = i / (16 * HH);
            float v = 0.f;
            if (k < FF) {
                int oj = permj(j);
                if (degnew(j) >= k + 1) v = Wi[(l * HH + oj) * FF + k];
            }
            g_Wi[i] = v;
        } else if (i < n1 + n2) {
            int t = i - n1;
            int j = t % HH;               // new output hidden index
            int k = (t / HH) % HH;        // new input hidden index
            int m = t / (HH * HH);        // l*4 + blk*2 + sub
            float v = 0.f;
            if (degnew(j) >= degnew(k))
                v = Wr[(m * HH + permj(j)) * HH + permj(k)];
            g_Wr[t] = v;
        } else if (i < n1 + n2 + n3) {
            int t = i - n1 - n2;
            int c = t % OUTWP;            // f*48+m
            int k = (t / OUTWP) % HH;     // new hidden index
            int l = t / (HH * OUTWP);
            int f = c / FP, m = c % FP;
            float v = 0.f;
            if (f < FF && m < MM) {
                if (f + 1 > degnew(k))
                    v = Wo[(l * OUTW + f * MM + m) * HH + permj(k)];
            }
            g_Wo[t] = v;
        } else if (i < n1 + n2 + n3 + n4) {
            int t = i - n1 - n2 - n3;
            int c = t % OUTWP;
            int l = t / OUTWP;
            int f = c / FP, m = c % FP;
            g_bo[t] = (f < FF && m < MM) ? bo[l * OUTW + f * MM + m] : 0.f;
        } else if (i < n1 + n2 + n3 + n4 + n5) {
            int t = i - n1 - n2 - n3 - n4;
            int j = t % HH;
            int l = t / HH;
            g_bi[t] = bi[l * HH + permj(j)];
        } else {
            int t = i - n1 - n2 - n3 - n4 - n5;
            int j = t % HH;
            int m = t / HH;
            g_br[t] = br[m * HH + permj(j)];
        }
    }
}

// ---------------------------------------------------------------------------
__device__ __forceinline__ void fma2(ull& d, ull a, ull b)
{
    asm("fma.rn.f32x2 %0, %1, %2, %0;" : "+l"(d) : "l"(a), "l"(b));
}
__device__ __forceinline__ ull pack2(float v)
{
    ull r; asm("mov.b64 %0, {%1, %1};" : "=l"(r) : "f"(v)); return r;
}
__device__ __forceinline__ ull packf2(float a, float b)
{
    ull r; asm("mov.b64 %0, {%1, %2};" : "=l"(r) : "f"(a), "f"(b)); return r;
}

// ---------------------------------------------------------------------------
template <int NP, bool VEC4>
__device__ __forceinline__ void loadW(ull (&w)[4][NP],
                                      const float* __restrict__ Wg,
                                      int wld, int c0, int k0)
{
#pragma unroll
    for (int kk = 0; kk < 4; kk++) {
        const float* wr = Wg + (k0 + kk) * wld + c0;
        if (VEC4) {
#pragma unroll
            for (int j = 0; j < NP; j += 2) {
                ulonglong2 v = __ldg((const ulonglong2*)(wr + 2 * j));
                w[kk][j] = v.x;
                w[kk][j + 1] = v.y;
            }
        } else {
#pragma unroll
            for (int j = 0; j < NP; j++)
                w[kk][j] = __ldg((const ull*)(wr + 2 * j));
        }
    }
}

// Compute one 4-wide k-chunk for 8 interleaved rows (row = rx + 16*i).
template <int NP, bool RELU>
__device__ __forceinline__ void computeChunk(ull (&acc)[8][NP],
                                             const float* __restrict__ As,
                                             int ald, int rx, int k0,
                                             const ull (&w)[4][NP])
{
#pragma unroll
    for (int i = 0; i < 8; i++) {
        float4 a = *(const float4*)&As[(rx + 16 * i) * ald + k0];
        if (RELU) {
            a.x = fmaxf(a.x, 0.f);
            a.y = fmaxf(a.y, 0.f);
            a.z = fmaxf(a.z, 0.f);
            a.w = fmaxf(a.w, 0.f);
        }
        ull a0 = pack2(a.x), a1 = pack2(a.y), a2 = pack2(a.z), a3 = pack2(a.w);
#pragma unroll
        for (int j = 0; j < NP; j++) fma2(acc[i][j], a0, w[0][j]);
#pragma unroll
        for (int j = 0; j < NP; j++) fma2(acc[i][j], a1, w[1][j]);
#pragma unroll
        for (int j = 0; j < NP; j++) fma2(acc[i][j], a2, w[2][j]);
#pragma unroll
        for (int j = 0; j < NP; j++) fma2(acc[i][j], a3, w[3][j]);
    }
}

// ---------------------------------------------------------------------------
// Packed-f32x2 GEMM, double-buffered, runtime k-end (multiple of 8; may be 0).
// Warp-uniform column ranges: col group = tid>>4 -> 16 adjacent cols per warp.
// Rows interleaved: thread handles rows rx + 16*i, i = 0..7.
// ---------------------------------------------------------------------------
template <int NC, bool VEC4, bool RELU, bool ACC>
__device__ __forceinline__ void gemm2(const float* __restrict__ As, int ald,
                                      const float* __restrict__ Wg, int wld,
                                      const float* __restrict__ bias,
                                      float* __restrict__ Cs, int cld,
                                      int rx, int c0, int kend)
{
    constexpr int NP = NC / 2;

    ull acc[8][NP];
#pragma unroll
    for (int j = 0; j < NP; j++) {
        float2 b = *(const float2*)&bias[c0 + 2 * j];
#pragma unroll
        for (int i = 0; i < 8; i++) {
            float2 p = make_float2(0.f, 0.f);
            if (ACC) p = *(const float2*)&Cs[(rx + 16 * i) * cld + c0 + 2 * j];
            acc[i][j] = packf2(b.x + p.x, b.y + p.y);
        }
    }

    if (kend > 0) {
        ull wa[4][NP], wb[4][NP];
        loadW<NP, VEC4>(wa, Wg, wld, c0, 0);
#pragma unroll 1
        for (int k0 = 0; k0 < kend; k0 += 8) {
            loadW<NP, VEC4>(wb, Wg, wld, c0, k0 + 4);
            computeChunk<NP, RELU>(acc, As, ald, rx, k0, wa);
            if (k0 + 8 < kend) loadW<NP, VEC4>(wa, Wg, wld, c0, k0 + 8);
            computeChunk<NP, RELU>(acc, As, ald, rx, k0 + 4, wb);
        }
    }

#pragma unroll
    for (int i = 0; i < 8; i++)
#pragma unroll
        for (int j = 0; j < NP; j++)
            *(float2*)&Cs[(rx + 16 * i) * cld + c0 + 2 * j] = *(float2*)&acc[i][j];
}

// ---------------------------------------------------------------------------
__device__ __forceinline__ float softplusf(float v)
{
    return (v > 15.f) ? v : log1pf(__expf(v));
}

// Rational-quadratic spline, register-only scratch. p = 47 raw params (smem).
__device__ void rqs_reg(const float* __restrict__ p,
                        float* __restrict__ xp, float* __restrict__ ldp)
{
    float x = *xp;
    bool inside = (x >= -TAILV) && (x <= TAILV);
    float xc = fminf(fmaxf(x, -TAILV), TAILV);

    float ew[NBINS], eh[NBINS];
    float mw = p[0], mh = p[16];
#pragma unroll
    for (int i = 1; i < NBINS; i++) { mw = fmaxf(mw, p[i]); mh = fmaxf(mh, p[16 + i]); }
    float Sw = 0.f, Sh = 0.f;
#pragma unroll
    for (int i = 0; i < NBINS; i++) {
        ew[i] = __expf(p[i] - mw);      Sw += ew[i];
        eh[i] = __expf(p[16 + i] - mh); Sh += eh[i];
    }
    float scw = (1.f - MINW * NBINS) / Sw;
    float sch = (1.f - MINH * NBINS) / Sh;

    int idx = 0;
    float cwlo = -TAILV, cwhi = TAILV;
    bool found = false;
    float cacc = 0.f;
#pragma unroll
    for (int i = 0; i < NBINS - 1; i++) {
        cacc += MINW + scw * ew[i];
        float cw = 6.f * cacc - 3.f;
        if (xc >= cw) { idx++; cwlo = cw; }
        else if (!found) { cwhi = cw; found = true; }
    }
    float chlo = -TAILV, chhi = TAILV;
    float hacc = 0.f;
#pragma unroll
    for (int i = 0; i < NBINS - 1; i++) {
        hacc += MINH + sch * eh[i];
        float ch = 6.f * hacc - 3.f;
        if (i == idx - 1) chlo = ch;
        if (i == idx)     chhi = ch;
    }

    float inw = cwhi - cwlo;
    float inh = chhi - chlo;
    float delta = inh / inw;
    float ind  = (idx == 0)          ? 1.f : MIND + softplusf(p[32 + idx - 1]);
    float ind1 = (idx == NBINS - 1)  ? 1.f : MIND + softplusf(p[32 + idx]);

    float th   = (xc - cwlo) / inw;
    float omt  = 1.f - th;
    float tomt = th * omt;
    float num  = inh * (delta * th * th + ind * tomt);
    float den  = delta + (ind + ind1 - 2.f * delta) * tomt;
    float y    = chlo + num / den;
    float dnum = delta * delta * (ind1 * th * th + 2.f * delta * tomt + ind * omt * omt);
    float lad  = __logf(dnum) - 2.f * __logf(den);

    *xp = inside ? y : x;
    if (inside) atomicAdd(ldp, lad);
}

// ---------------------------------------------------------------------------
__global__ void __launch_bounds__(NT, 1)
flow_kernel(const float* __restrict__ x_in,
            float* __restrict__ out, int batch)
{
    extern __shared__ float sm[];
    float* xs   = sm;                      // SPB * XL
    float* hbuf = xs + SPB * XL;           // SPB * TL
    float* tbuf = hbuf + SPB * TL;         // SPB * TL
    float* ldv  = tbuf + SPB * TL;         // SPB

    int tid = threadIdx.x;
    int rx  = tid & 15;                    // row group: rows rx + 16*i
    int tyc = tid >> 4;                    // column group (warp-uniform pairs)
    int base = blockIdx.x * SPB;

    // k-limits from degree-sorted columns
    const int c0r  = tyc * 8;                           // res/init col base
    const int dmax = degnew(c0r + 7);
    const int kres = (cumcnt(dmax) + 7) & ~7;           // residual GEMM k-end
    const int kini = (dmax + 7) & ~7;                   // init GEMM k-end (<=16)
    const int c0o  = tyc * 6;                           // out-head col base

    for (int i = tid; i < SPB * FF; i += NT) {
        int s = i / FF, f = i % FF;
        xs[s * XL + f] = x_in[(base + s) * FF + f];
    }
    for (int i = tid; i < SPB; i += NT) { xs[i * XL + FF] = 0.f; ldv[i] = 0.f; }
    __syncthreads();

    for (int l = 0; l < LL; l++) {
        // feature reversal (each thread owns a full row)
        if (tid < SPB) {
            float v[FF];
#pragma unroll
            for (int f = 0; f < FF; f++) v[f] = xs[tid * XL + f];
#pragma unroll
            for (int f = 0; f < FF; f++) xs[tid * XL + f] = v[FF - 1 - f];
        }
        __syncthreads();

        // h = xs @ Wi^T + bi
        gemm2<8, true, false, false>(xs, XL, g_Wi + l * 16 * HH, HH,
                                     g_bi + l * HH, hbuf, TL, rx, c0r, kini);
        __syncthreads();

        const float* wr = g_Wr + l * 4 * HH * HH;
        const float* br = g_br + l * 4 * HH;

        gemm2<8, true, true, false>(hbuf, TL, wr, HH, br,
                                    tbuf, TL, rx, c0r, kres);
        __syncthreads();
        gemm2<8, true, true, true>(tbuf, TL, wr + HH * HH, HH, br + HH,
                                   hbuf, TL, rx, c0r, kres);
        __syncthreads();
        gemm2<8, true, true, false>(hbuf, TL, wr + 2 * HH * HH, HH,
                                    br + 2 * HH, tbuf, TL, rx, c0r, kres);
        __syncthreads();
        gemm2<8, true, true, true>(tbuf, TL, wr + 3 * HH * HH, HH,
                                   br + 3 * HH, hbuf, TL, rx, c0r, kres);
        __syncthreads();

        // output head: 8 chunks of 2 padded features (96 cols), fused RQS
        for (int c = 0; c < 8; c++) {
            int f = 2 * c + (tyc >> 3);
            int kout = (f == 0 || f >= FF) ? 0 : ((cumcnt(f) + 7) & ~7);
            gemm2<6, false, false, false>(hbuf, TL,
                                          g_Wo + l * HH * OUTWP + c * 96,
                                          OUTWP,
                                          g_bo + l * OUTWP + c * 96,
                                          tbuf, TL, rx, c0o, kout);
            __syncthreads();
            {
                int s = tid >> 1, q = tid & 1;
                int fr = 2 * c + q;
                if (fr < FF)
                    rqs_reg(&tbuf[s * TL + q * FP], &xs[s * XL + fr], &ldv[s]);
            }
            __syncthreads();
        }
    }

    for (int i = tid; i < SPB * FF; i += NT) {
        int s = i / FF, f = i % FF;
        out[(base + s) * FF + f] = xs[s * XL + f];
    }
    if (tid < SPB) out[batch * FF + base + tid] = ldv[tid];
}

static const int SMEM_BYTES = (SPB * XL + 2 * SPB * TL + SPB) * (int)sizeof(float);

extern "C" void kernel_launch(void* const* d_in, const int* in_sizes, int n_in,
                              void* d_out, int out_size)
{
    const float* x  = (const float*)d_in[0];
    const float* Wi = (const float*)d_in[1];
    const float* bi = (const float*)d_in[2];
    const float* Wr = (const float*)d_in[3];
    const float* br = (const float*)d_in[4];
    const float* Wo = (const float*)d_in[5];
    const float* bo = (const float*)d_in[6];
    float* out = (float*)d_out;

    int batch = in_sizes[0] / FF;

    cudaFuncSetAttribute(flow_kernel,
                         cudaFuncAttributeMaxDynamicSharedMemorySize, SMEM_BYTES);

    prep_kernel<<<2048, 256>>>(Wi, bi, Wr, br, Wo, bo);
    flow_kernel<<<batch / SPB, NT, SMEM_BYTES>>>(x, out, batch);
}

// round 8
// speedup vs baseline: 1.5258x; 1.0343x over previous
#include <cuda_runtime.h>
#include <math.h>

#define FF 15
#define HH 128
#define LL 12
#define NBINS 16
#define MM 47            // 3*NB - 1
#define OUTW (FF*MM)     // 705
#define FP 48            // padded per-feature width
#define NFP 16           // padded feature count
#define OUTWP (NFP*FP)   // 768
#define TAILV 3.0f
#define MINW 0.001f
#define MINH 0.001f
#define MIND 0.001f
#define SPB 128          // samples per block
#define TL 132           // row stride for h/t buffers
#define XL 16            // row stride for x buffer
#define NT 256           // threads per CTA

typedef unsigned long long ull;

// Hidden units permuted sorted-by-degree (exact similarity transform).
__host__ __device__ __forceinline__ int cumcnt(int d)
{
    return (d <= 2) ? 10 * d : 9 * d + 2;
}
__host__ __device__ __forceinline__ int degnew(int j)
{
    return (j < 20) ? (j / 10 + 1) : ((j - 2) / 9 + 1);
}
__host__ __device__ __forceinline__ int permj(int j)
{
    int d = degnew(j);
    int t = j - cumcnt(d - 1);
    return (d - 1) + 14 * t;
}
__host__ __device__ __forceinline__ int r8(int x) { return (x + 7) & ~7; }

// Pre-masked, transposed, permuted, padded weights (scratch)
__device__ float g_Wi[LL * 16 * HH];        // [l][k(16)][j']
__device__ float g_Wr[LL * 4 * HH * HH];    // [l][blk*2+sub][k'][j']
__device__ float g_Wo[LL * HH * OUTWP];     // [l][k'][f*48+m]
__device__ float g_bo[LL * OUTWP];          // padded out bias
__device__ float g_bi[LL * HH];             // permuted init bias
__device__ float g_br[LL * 4 * HH];         // permuted res bias

// ---------------------------------------------------------------------------
__global__ void prep_kernel(const float* __restrict__ Wi,
                            const float* __restrict__ bi,
                            const float* __restrict__ Wr,
                            const float* __restrict__ br,
                            const float* __restrict__ Wo,
                            const float* __restrict__ bo)
{
    const int n1 = LL * 16 * HH;
    const int n2 = LL * 4 * HH * HH;
    const int n3 = LL * HH * OUTWP;
    const int n4 = LL * OUTWP;
    const int n5 = LL * HH;
    const int n6 = LL * 4 * HH;
    const int ntot = n1 + n2 + n3 + n4 + n5 + n6;
    for (int i = blockIdx.x * blockDim.x + threadIdx.x; i < ntot;
         i += gridDim.x * blockDim.x) {
        if (i < n1) {
            int j = i % HH;
            int k = (i / HH) % 16;
            int l = i / (16 * HH);
            float v = 0.f;
            if (k < FF) {
                int oj = permj(j);
                if (degnew(j) >= k + 1) v = Wi[(l * HH + oj) * FF + k];
            }
            g_Wi[i] = v;
        } else if (i < n1 + n2) {
            int t = i - n1;
            int j = t % HH;
            int k = (t / HH) % HH;
            int m = t / (HH * HH);
            float v = 0.f;
            if (degnew(j) >= degnew(k))
                v = Wr[(m * HH + permj(j)) * HH + permj(k)];
            g_Wr[t] = v;
        } else if (i < n1 + n2 + n3) {
            int t = i - n1 - n2;
            int c = t % OUTWP;
            int k = (t / OUTWP) % HH;
            int l = t / (HH * OUTWP);
            int f = c / FP, m = c % FP;
            float v = 0.f;
            if (f < FF && m < MM) {
                if (f + 1 > degnew(k))
                    v = Wo[(l * OUTW + f * MM + m) * HH + permj(k)];
            }
            g_Wo[t] = v;
        } else if (i < n1 + n2 + n3 + n4) {
            int t = i - n1 - n2 - n3;
            int c = t % OUTWP;
            int l = t / OUTWP;
            int f = c / FP, m = c % FP;
            g_bo[t] = (f < FF && m < MM) ? bo[l * OUTW + f * MM + m] : 0.f;
        } else if (i < n1 + n2 + n3 + n4 + n5) {
            int t = i - n1 - n2 - n3 - n4;
            int j = t % HH;
            int l = t / HH;
            g_bi[t] = bi[l * HH + permj(j)];
        } else {
            int t = i - n1 - n2 - n3 - n4 - n5;
            int j = t % HH;
            int m = t / HH;
            g_br[t] = br[m * HH + permj(j)];
        }
    }
}

// ---------------------------------------------------------------------------
__device__ __forceinline__ void fma2(ull& d, ull a, ull b)
{
    asm("fma.rn.f32x2 %0, %1, %2, %0;" : "+l"(d) : "l"(a), "l"(b));
}
__device__ __forceinline__ ull pack2(float v)
{
    ull r; asm("mov.b64 %0, {%1, %1};" : "=l"(r) : "f"(v)); return r;
}
__device__ __forceinline__ ull packf2(float a, float b)
{
    ull r; asm("mov.b64 %0, {%1, %2};" : "=l"(r) : "f"(a), "f"(b)); return r;
}

// ---------------------------------------------------------------------------
template <int NP, bool VEC4>
__device__ __forceinline__ void loadW(ull (&w)[4][NP],
                                      const float* __restrict__ Wg,
                                      int wld, int c0, int k0)
{
#pragma unroll
    for (int kk = 0; kk < 4; kk++) {
        const float* wr = Wg + (k0 + kk) * wld + c0;
        if (VEC4) {
#pragma unroll
            for (int j = 0; j < NP; j += 2) {
                ulonglong2 v = __ldg((const ulonglong2*)(wr + 2 * j));
                w[kk][j] = v.x;
                w[kk][j + 1] = v.y;
            }
        } else {
#pragma unroll
            for (int j = 0; j < NP; j++)
                w[kk][j] = __ldg((const ull*)(wr + 2 * j));
        }
    }
}

// Compute one 4-wide k-chunk for 8 interleaved rows (row = rx + 16*i).
template <int NP, bool RELU>
__device__ __forceinline__ void computeChunk(ull (&acc)[8][NP],
                                             const float* __restrict__ As,
                                             int ald, int rx, int k0,
                                             const ull (&w)[4][NP])
{
#pragma unroll
    for (int i = 0; i < 8; i++) {
        float4 a = *(const float4*)&As[(rx + 16 * i) * ald + k0];
        if (RELU) {
            a.x = fmaxf(a.x, 0.f);
            a.y = fmaxf(a.y, 0.f);
            a.z = fmaxf(a.z, 0.f);
            a.w = fmaxf(a.w, 0.f);
        }
        ull a0 = pack2(a.x), a1 = pack2(a.y), a2 = pack2(a.z), a3 = pack2(a.w);
#pragma unroll
        for (int j = 0; j < NP; j++) fma2(acc[i][j], a0, w[0][j]);
#pragma unroll
        for (int j = 0; j < NP; j++) fma2(acc[i][j], a1, w[1][j]);
#pragma unroll
        for (int j = 0; j < NP; j++) fma2(acc[i][j], a2, w[2][j]);
#pragma unroll
        for (int j = 0; j < NP; j++) fma2(acc[i][j], a3, w[3][j]);
    }
}

// ---------------------------------------------------------------------------
// Packed-f32x2 GEMM, double-buffered, runtime k-end (multiple of 8; may be 0).
// Writes C columns [cs0, cs0+NC); reads W/bias columns [c0, c0+NC).
// ---------------------------------------------------------------------------
template <int NC, bool VEC4, bool RELU, bool ACC>
__device__ __forceinline__ void gemm2(const float* __restrict__ As, int ald,
                                      const float* __restrict__ Wg, int wld,
                                      const float* __restrict__ bias,
                                      float* __restrict__ Cs, int cld,
                                      int rx, int c0, int cs0, int kend)
{
    constexpr int NP = NC / 2;

    ull acc[8][NP];
#pragma unroll
    for (int j = 0; j < NP; j++) {
        float2 b = *(const float2*)&bias[c0 + 2 * j];
#pragma unroll
        for (int i = 0; i < 8; i++) {
            float2 p = make_float2(0.f, 0.f);
            if (ACC) p = *(const float2*)&Cs[(rx + 16 * i) * cld + cs0 + 2 * j];
            acc[i][j] = packf2(b.x + p.x, b.y + p.y);
        }
    }

    if (kend > 0) {
        ull wa[4][NP], wb[4][NP];
        loadW<NP, VEC4>(wa, Wg, wld, c0, 0);
#pragma unroll 1
        for (int k0 = 0; k0 < kend; k0 += 8) {
            loadW<NP, VEC4>(wb, Wg, wld, c0, k0 + 4);
            computeChunk<NP, RELU>(acc, As, ald, rx, k0, wa);
            if (k0 + 8 < kend) loadW<NP, VEC4>(wa, Wg, wld, c0, k0 + 8);
            computeChunk<NP, RELU>(acc, As, ald, rx, k0 + 4, wb);
        }
    }

#pragma unroll
    for (int i = 0; i < 8; i++)
#pragma unroll
        for (int j = 0; j < NP; j++)
            *(float2*)&Cs[(rx + 16 * i) * cld + cs0 + 2 * j] = *(float2*)&acc[i][j];
}

// ---------------------------------------------------------------------------
__device__ __forceinline__ float softplusf(float v)
{
    return (v > 15.f) ? v : log1pf(__expf(v));
}

// Rational-quadratic spline, register-only scratch. p = 47 raw params (smem).
__device__ void rqs_reg(const float* __restrict__ p,
                        float* __restrict__ xp, float* __restrict__ ldp)
{
    float x = *xp;
    bool inside = (x >= -TAILV) && (x <= TAILV);
    float xc = fminf(fmaxf(x, -TAILV), TAILV);

    float ew[NBINS], eh[NBINS];
    float mw = p[0], mh = p[16];
#pragma unroll
    for (int i = 1; i < NBINS; i++) { mw = fmaxf(mw, p[i]); mh = fmaxf(mh, p[16 + i]); }
    float Sw = 0.f, Sh = 0.f;
#pragma unroll
    for (int i = 0; i < NBINS; i++) {
        ew[i] = __expf(p[i] - mw);      Sw += ew[i];
        eh[i] = __expf(p[16 + i] - mh); Sh += eh[i];
    }
    float scw = (1.f - MINW * NBINS) / Sw;
    float sch = (1.f - MINH * NBINS) / Sh;

    int idx = 0;
    float cwlo = -TAILV, cwhi = TAILV;
    bool found = false;
    float cacc = 0.f;
#pragma unroll
    for (int i = 0; i < NBINS - 1; i++) {
        cacc += MINW + scw * ew[i];
        float cw = 6.f * cacc - 3.f;
        if (xc >= cw) { idx++; cwlo = cw; }
        else if (!found) { cwhi = cw; found = true; }
    }
    float chlo = -TAILV, chhi = TAILV;
    float hacc = 0.f;
#pragma unroll
    for (int i = 0; i < NBINS - 1; i++) {
        hacc += MINH + sch * eh[i];
        float ch = 6.f * hacc - 3.f;
        if (i == idx - 1) chlo = ch;
        if (i == idx)     chhi = ch;
    }

    float inw = cwhi - cwlo;
    float inh = chhi - chlo;
    float delta = inh / inw;
    float ind  = (idx == 0)          ? 1.f : MIND + softplusf(p[32 + idx - 1]);
    float ind1 = (idx == NBINS - 1)  ? 1.f : MIND + softplusf(p[32 + idx]);

    float th   = (xc - cwlo) / inw;
    float omt  = 1.f - th;
    float tomt = th * omt;
    float num  = inh * (delta * th * th + ind * tomt);
    float den  = delta + (ind + ind1 - 2.f * delta) * tomt;
    float y    = chlo + num / den;
    float dnum = delta * delta * (ind1 * th * th + 2.f * delta * tomt + ind * omt * omt);
    float lad  = __logf(dnum) - 2.f * __logf(den);

    *xp = inside ? y : x;
    if (inside) atomicAdd(ldp, lad);
}

// ---------------------------------------------------------------------------
__global__ void __launch_bounds__(NT, 1)
flow_kernel(const float* __restrict__ x_in,
            float* __restrict__ out, int batch)
{
    extern __shared__ float sm[];
    float* xs   = sm;                      // SPB * XL
    float* hbuf = xs + SPB * XL;           // SPB * TL
    float* tbuf = hbuf + SPB * TL;         // SPB * TL
    float* ldv  = tbuf + SPB * TL;         // SPB

    int tid = threadIdx.x;
    int rx  = tid & 15;                    // row group: rows rx + 16*i
    int tyc = tid >> 4;                    // column group id (0..15)
    int base = blockIdx.x * SPB;

    // Split-phase column assignment over 32 groups of 4 columns:
    // phase A = group tyc (low degree), phase B = group 31-tyc (high degree).
    const int cA = tyc * 4;
    const int cB = (31 - tyc) * 4;
    const int dA = degnew(cA + 3);
    const int dB = degnew(cB + 3);
    const int kresA = r8(cumcnt(dA));
    const int kresB = r8(cumcnt(dB));
    const int kiniA = min(r8(dA), 16);
    const int kiniB = min(r8(dB), 16);

    for (int i = tid; i < SPB * FF; i += NT) {
        int s = i / FF, f = i % FF;
        xs[s * XL + f] = x_in[(base + s) * FF + f];
    }
    for (int i = tid; i < SPB; i += NT) { xs[i * XL + FF] = 0.f; ldv[i] = 0.f; }
    __syncthreads();

    for (int l = 0; l < LL; l++) {
        // feature reversal (each thread owns a full row)
        if (tid < SPB) {
            float v[FF];
#pragma unroll
            for (int f = 0; f < FF; f++) v[f] = xs[tid * XL + f];
#pragma unroll
            for (int f = 0; f < FF; f++) xs[tid * XL + f] = v[FF - 1 - f];
        }
        __syncthreads();

        // h = xs @ Wi^T + bi  (two balanced phases)
        {
            const float* wi = g_Wi + l * 16 * HH;
            const float* bi = g_bi + l * HH;
            gemm2<4, true, false, false>(xs, XL, wi, HH, bi, hbuf, TL,
                                         rx, cA, cA, kiniA);
            gemm2<4, true, false, false>(xs, XL, wi, HH, bi, hbuf, TL,
                                         rx, cB, cB, kiniB);
        }
        __syncthreads();

        const float* wr = g_Wr + l * 4 * HH * HH;
        const float* br = g_br + l * 4 * HH;

#pragma unroll
        for (int sub = 0; sub < 4; sub++) {
            const float* w = wr + sub * HH * HH;
            const float* b = br + sub * HH;
            const float* src = (sub & 1) ? tbuf : hbuf;
            float* dst = (sub & 1) ? hbuf : tbuf;
            if (sub & 1) {
                gemm2<4, true, true, true>(src, TL, w, HH, b, dst, TL,
                                           rx, cA, cA, kresA);
                gemm2<4, true, true, true>(src, TL, w, HH, b, dst, TL,
                                           rx, cB, cB, kresB);
            } else {
                gemm2<4, true, true, false>(src, TL, w, HH, b, dst, TL,
                                            rx, cA, cA, kresA);
                gemm2<4, true, true, false>(src, TL, w, HH, b, dst, TL,
                                            rx, cB, cB, kresB);
            }
            __syncthreads();
        }

        // output head: chunks of 2 features, sorted by descending k-work.
        // chunk c: fa = 14-2c (warps 0-3), fb = 13-2c (warps 4-7; c=7 -> pad)
        for (int c = 0; c < 8; c++) {
            int fa = 14 - 2 * c;
            int fb = 13 - 2 * c;           // c == 7 -> fb = -1 (pad)
            int f  = (tyc < 8) ? fa : (fb < 0 ? FF : fb);
            int kout = (f == 0 || f >= FF) ? 0 : r8(cumcnt(f));
            int cw = f * FP + (tyc & 7) * 6;        // weight/bias column
            int cs = ((tyc < 8) ? 0 : FP) + (tyc & 7) * 6;  // tbuf column
            gemm2<6, false, false, false>(hbuf, TL,
                                          g_Wo + l * HH * OUTWP, OUTWP,
                                          g_bo + l * OUTWP,
                                          tbuf, TL, rx, cw, cs, kout);
            __syncthreads();
            {
                int s = tid >> 1, q = tid & 1;
                int fr = q ? fb : fa;
                if (fr >= 0)
                    rqs_reg(&tbuf[s * TL + q * FP], &xs[s * XL + fr], &ldv[s]);
            }
            __syncthreads();
        }
    }

    for (int i = tid; i < SPB * FF; i += NT) {
        int s = i / FF, f = i % FF;
        out[(base + s) * FF + f] = xs[s * XL + f];
    }
    if (tid < SPB) out[batch * FF + base + tid] = ldv[tid];
}

static const int SMEM_BYTES = (SPB * XL + 2 * SPB * TL + SPB) * (int)sizeof(float);

extern "C" void kernel_launch(void* const* d_in, const int* in_sizes, int n_in,
                              void* d_out, int out_size)
{
    const float* x  = (const float*)d_in[0];
    const float* Wi = (const float*)d_in[1];
    const float* bi = (const float*)d_in[2];
    const float* Wr = (const float*)d_in[3];
    const float* br = (const float*)d_in[4];
    const float* Wo = (const float*)d_in[5];
    const float* bo = (const float*)d_in[6];
    float* out = (float*)d_out;

    int batch = in_sizes[0] / FF;

    cudaFuncSetAttribute(flow_kernel,
                         cudaFuncAttributeMaxDynamicSharedMemorySize, SMEM_BYTES);

    prep_kernel<<<2048, 256>>>(Wi, bi, Wr, br, Wo, bo);
    flow_kernel<<<batch / SPB, NT, SMEM_BYTES>>>(x, out, batch);
}